// round 15
// baseline (speedup 1.0000x reference)
#include <cuda_runtime.h>
#include <math.h>

#define Bsz 16
#define Tn 16
#define FDIM 64
#define ODIM 8
#define NQ 10
#define NA 4
#define NROTS 80
#define QROTS 40
#define NS 1024
#define NANC 16
#define STATE_PER_B (NS*NANC)
#define TOTAL_AMPS (Bsz*STATE_PER_B)
#define NCTA 256

typedef unsigned long long u64;

__device__ float4 g_state4[TOTAL_AMPS/2];
#define G_STATE  ((float2*)g_state4)
#define G_STATEU ((u64*)g_state4)
__device__ float2 g_M[3][256];
__device__ float  g_expart[NCTA*30];
__device__ unsigned g_bcnt[16];
__device__ unsigned g_bsns[16];

// ------------------------------------------------------- packed f32x2 ops ---
__device__ __forceinline__ u64 pk2(float x, float y) {
    u64 r; asm("mov.b64 %0, {%1, %2};" : "=l"(r) : "f"(x), "f"(y)); return r;
}
__device__ __forceinline__ float2 upk(u64 a) {
    float2 f; asm("mov.b64 {%0, %1}, %2;" : "=f"(f.x), "=f"(f.y) : "l"(a)); return f;
}
__device__ __forceinline__ u64 mul2(u64 a, u64 b) {
    u64 d; asm("mul.rn.f32x2 %0, %1, %2;" : "=l"(d) : "l"(a), "l"(b)); return d;
}
__device__ __forceinline__ u64 fma2(u64 a, u64 b, u64 c) {
    u64 d; asm("fma.rn.f32x2 %0, %1, %2, %3;" : "=l"(d) : "l"(a), "l"(b), "l"(c)); return d;
}
__device__ __forceinline__ u64 swap2(u64 a) {
    float2 f = upk(a); return pk2(f.y, f.x);
}

// ----------------------------------------------------- per-batch barrier ----
__device__ __forceinline__ void bbar(int b, unsigned target)
{
    __syncthreads();
    if (threadIdx.x == 0) {
        __threadfence();
        unsigned arrived = atomicAdd(&g_bcnt[b], 1u) + 1u;
        if (arrived == 16u) {
            g_bcnt[b] = 0u;
            __threadfence();
            atomicExch(&g_bsns[b], target);
        } else {
            while ((int)(*(volatile unsigned*)&g_bsns[b] - target) < 0) { }
        }
        __threadfence();
    }
    __syncthreads();
}

// ----------------------------------------------------- pair-scoped barrier --
// wb=0 pairs warps (0,1),(2,3) -> ids 1,2 ; wb=1 pairs (0,2),(1,3) -> ids 3,4.
__device__ __forceinline__ void pbar(int tid, int wb)
{
    int w = tid >> 5;
    int id = wb ? (3 + (w & 1)) : (1 + (w >> 1));
    asm volatile("bar.sync %0, %1;" :: "r"(id), "r"(64) : "memory");
}

// ------------------------------------------------------- gate primitives ----
// layout: amplitude s: lane = s[4:0], reg = s[7:5] (8 u64/lane), warp = s[9:8].

template<int PB>
__device__ __forceinline__ void ry_reg(u64* v, float cc, float ss)
{
    u64 cc2 = pk2(cc, cc), ss2 = pk2(ss, ss), nss2 = pk2(-ss, -ss);
    #pragma unroll
    for (int m = 0; m < 4; ++m) {
        int i0 = ((m >> PB) << (PB+1)) | (m & ((1 << PB) - 1));
        int i1 = i0 | (1 << PB);
        u64 a0 = v[i0], a1 = v[i1];
        v[i0] = fma2(cc2, a0, mul2(nss2, a1));
        v[i1] = fma2(cc2, a1, mul2(ss2, a0));
    }
}

__device__ __forceinline__ void ry_lane(u64* v, int pl, float cc, float ss, int lane)
{
    float sg = ((lane >> pl) & 1) ? ss : -ss;
    u64 cc2 = pk2(cc, cc), sg2 = pk2(sg, sg);
    int mk = 1 << pl;
    #pragma unroll
    for (int q = 0; q < 8; ++q) {
        float2 f = upk(v[q]);
        float px = __shfl_xor_sync(0xffffffffu, f.x, mk);
        float py = __shfl_xor_sync(0xffffffffu, f.y, mk);
        v[q] = fma2(cc2, v[q], mul2(sg2, pk2(px, py)));
    }
}

template<int PCB, int PTB>
__device__ __forceinline__ void crx_rr(u64* v, float cc, float ss)
{
    u64 cc2 = pk2(cc, cc), ssv2 = pk2(ss, -ss);
    #pragma unroll
    for (int i = 0; i < 8; ++i) {
        if ((((i >> PCB) & 1) == 1) && (((i >> PTB) & 1) == 0)) {
            int i1 = i | (1 << PTB);
            u64 a0 = v[i], a1 = v[i1];
            v[i]  = fma2(cc2, a0, mul2(ssv2, swap2(a1)));
            v[i1] = fma2(cc2, a1, mul2(ssv2, swap2(a0)));
        }
    }
}

__device__ __forceinline__ void crx_shfl(u64* v, int pt, bool act, float cc, float ss)
{
    float ccl = act ? cc : 1.f, ssl = act ? ss : 0.f;
    u64 cc2 = pk2(ccl, ccl), ssv2 = pk2(ssl, -ssl);
    int mk = 1 << pt;
    #pragma unroll
    for (int q = 0; q < 8; ++q) {
        float2 f = upk(v[q]);
        float px = __shfl_xor_sync(0xffffffffu, f.x, mk);
        float py = __shfl_xor_sync(0xffffffffu, f.y, mk);
        v[q] = fma2(cc2, v[q], mul2(ssv2, pk2(py, px)));
    }
}

template<int PCB>
__device__ __forceinline__ void crx_rl(u64* v, int pt, float cc, float ss)
{
    u64 cc2 = pk2(cc, cc), ssv2 = pk2(ss, -ss);
    int mk = 1 << pt;
    #pragma unroll
    for (int q = 0; q < 8; ++q) {
        if ((q >> PCB) & 1) {
            float2 f = upk(v[q]);
            float px = __shfl_xor_sync(0xffffffffu, f.x, mk);
            float py = __shfl_xor_sync(0xffffffffu, f.y, mk);
            v[q] = fma2(cc2, v[q], mul2(ssv2, pk2(py, px)));
        }
    }
}

template<int PTB>
__device__ __forceinline__ void crx_reg_tgt(u64* v, bool act, float cc, float ss)
{
    float ccl = act ? cc : 1.f, ssl = act ? ss : 0.f;
    u64 cc2 = pk2(ccl, ccl), ssv2 = pk2(ssl, -ssl);
    #pragma unroll
    for (int m = 0; m < 4; ++m) {
        int i0 = ((m >> PTB) << (PTB+1)) | (m & ((1 << PTB) - 1));
        int i1 = i0 | (1 << PTB);
        u64 a0 = v[i0], a1 = v[i1];
        v[i0] = fma2(cc2, a0, mul2(ssv2, swap2(a1)));
        v[i1] = fma2(cc2, a1, mul2(ssv2, swap2(a0)));
    }
}

// ----- cross-warp exchange gates (quad-buffered smem, pair barriers) --------
// Quad buffer is required: with pair-scoped barriers, buffer reuse at distance
// k is safe iff some exchange in (n, n+k) shares e_n's pairing. Exchange
// pairing patterns are (1,0)* forward and (0,1,1,0)* adjoint; k=4 satisfies
// the condition for every n in both.
struct Xch {
    u64* base; int tog; int tid;
    __device__ __forceinline__ u64* next() { u64* p = base + ((tog & 3) << 10); ++tog; return p; }
};

__device__ __forceinline__ void ry_warp(u64* v, Xch& X, int wb, float cc, float ss)
{
    u64* b = X.next();
    int tid = X.tid, xv = 32 << wb;
    #pragma unroll
    for (int i = 0; i < 8; ++i) b[i*128 + tid] = v[i];
    pbar(tid, wb);
    float sg = ((tid >> (5 + wb)) & 1) ? ss : -ss;
    u64 cc2 = pk2(cc, cc), sg2 = pk2(sg, sg);
    #pragma unroll
    for (int i = 0; i < 8; ++i)
        v[i] = fma2(cc2, v[i], mul2(sg2, b[i*128 + (tid ^ xv)]));
}

__device__ __forceinline__ void crx_warp_tgt(u64* v, Xch& X, int twb, bool act, float cc, float ss)
{
    u64* b = X.next();
    int tid = X.tid, xv = 32 << twb;
    #pragma unroll
    for (int i = 0; i < 8; ++i) b[i*128 + tid] = v[i];
    pbar(tid, twb);
    float ccl = act ? cc : 1.f, ssl = act ? ss : 0.f;
    u64 cc2 = pk2(ccl, ccl), ssv2 = pk2(ssl, -ssl);
    #pragma unroll
    for (int i = 0; i < 8; ++i)
        v[i] = fma2(cc2, v[i], mul2(ssv2, swap2(b[i*128 + (tid ^ xv)])));
}

__device__ __forceinline__ void crx_rw(u64* v, Xch& X, int twb, float cc, float ss)
{
    u64* b = X.next();
    int tid = X.tid, xv = 32 << twb;
    #pragma unroll
    for (int i = 0; i < 4; ++i) b[i*128 + tid] = v[4 + i];
    pbar(tid, twb);
    u64 cc2 = pk2(cc, cc), ssv2 = pk2(ss, -ss);
    #pragma unroll
    for (int i = 0; i < 4; ++i)
        v[4 + i] = fma2(cc2, v[4 + i], mul2(ssv2, swap2(b[i*128 + (tid ^ xv)])));
}

// -------------------------------------------------------- layer pieces ------
#define SS(A) (sgn*(A).y)

__device__ __forceinline__ void ry_all(u64* v, Xch& X, const float2* __restrict__ ang,
                                       float sgn, int lane)
{
    ry_warp(v, X, 1, ang[0].x, SS(ang[0]));
    ry_warp(v, X, 0, ang[1].x, SS(ang[1]));
    ry_reg<2>(v, ang[2].x, SS(ang[2]));
    ry_reg<1>(v, ang[3].x, SS(ang[3]));
    ry_reg<0>(v, ang[4].x, SS(ang[4]));
    #pragma unroll 1
    for (int pl = 4; pl >= 0; --pl) {
        float2 cs = ang[9 - pl];
        ry_lane(v, pl, cs.x, sgn*cs.y, lane);
    }
}

__device__ __forceinline__ void ring_a(u64* v, Xch& X, const float2* __restrict__ ang,
                                       float sgn, int lane, int tid, bool rev)
{
    if (!rev) {
        crx_warp_tgt(v, X, 1, lane & 1, ang[0].x, SS(ang[0]));
        crx_shfl(v, 0, (lane >> 1) & 1, ang[1].x, SS(ang[1]));
        crx_shfl(v, 1, (lane >> 2) & 1, ang[2].x, SS(ang[2]));
        crx_shfl(v, 2, (lane >> 3) & 1, ang[3].x, SS(ang[3]));
        crx_shfl(v, 3, (lane >> 4) & 1, ang[4].x, SS(ang[4]));
        crx_rl<0>(v, 4, ang[5].x, SS(ang[5]));
        crx_rr<1,0>(v, ang[6].x, SS(ang[6]));
        crx_rr<2,1>(v, ang[7].x, SS(ang[7]));
        crx_reg_tgt<2>(v, (tid >> 5) & 1, ang[8].x, SS(ang[8]));
        crx_warp_tgt(v, X, 0, (tid >> 6) & 1, ang[9].x, SS(ang[9]));
    } else {
        crx_warp_tgt(v, X, 0, (tid >> 6) & 1, ang[9].x, SS(ang[9]));
        crx_reg_tgt<2>(v, (tid >> 5) & 1, ang[8].x, SS(ang[8]));
        crx_rr<2,1>(v, ang[7].x, SS(ang[7]));
        crx_rr<1,0>(v, ang[6].x, SS(ang[6]));
        crx_rl<0>(v, 4, ang[5].x, SS(ang[5]));
        crx_shfl(v, 3, (lane >> 4) & 1, ang[4].x, SS(ang[4]));
        crx_shfl(v, 2, (lane >> 3) & 1, ang[3].x, SS(ang[3]));
        crx_shfl(v, 1, (lane >> 2) & 1, ang[2].x, SS(ang[2]));
        crx_shfl(v, 0, (lane >> 1) & 1, ang[1].x, SS(ang[1]));
        crx_warp_tgt(v, X, 1, lane & 1, ang[0].x, SS(ang[0]));
    }
}

__device__ __forceinline__ void ring_b(u64* v, Xch& X, const float2* __restrict__ ang,
                                       float sgn, int lane, int tid, bool rev)
{
    if (!rev) {
        crx_shfl(v, 1, lane & 1, ang[0].x, SS(ang[0]));
        crx_shfl(v, 0, (tid >> 6) & 1, ang[1].x, SS(ang[1]));
        crx_warp_tgt(v, X, 1, (tid >> 5) & 1, ang[2].x, SS(ang[2]));
        crx_rw(v, X, 0, ang[3].x, SS(ang[3]));
        crx_rr<1,2>(v, ang[4].x, SS(ang[4]));
        crx_rr<0,1>(v, ang[5].x, SS(ang[5]));
        crx_reg_tgt<0>(v, (lane >> 4) & 1, ang[6].x, SS(ang[6]));
        crx_shfl(v, 4, (lane >> 3) & 1, ang[7].x, SS(ang[7]));
        crx_shfl(v, 3, (lane >> 2) & 1, ang[8].x, SS(ang[8]));
        crx_shfl(v, 2, (lane >> 1) & 1, ang[9].x, SS(ang[9]));
    } else {
        crx_shfl(v, 2, (lane >> 1) & 1, ang[9].x, SS(ang[9]));
        crx_shfl(v, 3, (lane >> 2) & 1, ang[8].x, SS(ang[8]));
        crx_shfl(v, 4, (lane >> 3) & 1, ang[7].x, SS(ang[7]));
        crx_reg_tgt<0>(v, (lane >> 4) & 1, ang[6].x, SS(ang[6]));
        crx_rr<0,1>(v, ang[5].x, SS(ang[5]));
        crx_rr<1,2>(v, ang[4].x, SS(ang[4]));
        crx_rw(v, X, 0, ang[3].x, SS(ang[3]));
        crx_warp_tgt(v, X, 1, (tid >> 5) & 1, ang[2].x, SS(ang[2]));
        crx_shfl(v, 0, (tid >> 6) & 1, ang[1].x, SS(ang[1]));
        crx_shfl(v, 1, lane & 1, ang[0].x, SS(ang[0]));
    }
}

// --------------------------------------------------- in-register expvals ----
__device__ void exp_partial(int c, int tid, int lane, u64* v, u64* xbuf)
{
    __syncthreads();    // quad buffers may still be in use by other pairs
    float X[10], Y[10], Z[10];
    #pragma unroll
    for (int i = 0; i < 10; ++i) { X[i] = 0.f; Y[i] = 0.f; Z[i] = 0.f; }

    #pragma unroll
    for (int p = 0; p < 5; ++p) {
        int i = 9 - p;
        int mk = 1 << p;
        float sg = ((lane >> p) & 1) ? -1.f : 1.f;
        #pragma unroll
        for (int q = 0; q < 8; ++q) {
            float2 f = upk(v[q]);
            float px = __shfl_xor_sync(0xffffffffu, f.x, mk);
            float py = __shfl_xor_sync(0xffffffffu, f.y, mk);
            X[i] += f.x*px + f.y*py;
            Y[i] += sg*(f.x*py - f.y*px);
            Z[i] += sg*(f.x*f.x + f.y*f.y);
        }
    }
    #pragma unroll
    for (int pb = 0; pb < 3; ++pb) {
        int i = 4 - pb;
        #pragma unroll
        for (int m = 0; m < 4; ++m) {
            int i0 = ((m >> pb) << (pb+1)) | (m & ((1 << pb) - 1));
            int i1 = i0 | (1 << pb);
            float2 a = upk(v[i0]), cc = upk(v[i1]);
            X[i] += 2.f*(a.x*cc.x + a.y*cc.y);
            Y[i] += 2.f*(a.x*cc.y - a.y*cc.x);
            Z[i] += (a.x*a.x + a.y*a.y) - (cc.x*cc.x + cc.y*cc.y);
        }
    }
    #pragma unroll
    for (int q = 0; q < 8; ++q) xbuf[q*128 + tid] = v[q];
    __syncthreads();
    #pragma unroll
    for (int wb = 0; wb < 2; ++wb) {
        int i = 1 - wb;
        int pr = tid ^ (32 << wb);
        float sg = ((tid >> (5 + wb)) & 1) ? -1.f : 1.f;
        #pragma unroll
        for (int q = 0; q < 8; ++q) {
            float2 g = upk(xbuf[q*128 + pr]);
            float2 f = upk(v[q]);
            X[i] += f.x*g.x + f.y*g.y;
            Y[i] += sg*(f.x*g.y - f.y*g.x);
            Z[i] += sg*(f.x*f.x + f.y*f.y);
        }
    }
    __syncthreads();
    #pragma unroll
    for (int i = 0; i < 10; ++i) {
        #pragma unroll
        for (int off = 16; off; off >>= 1) {
            X[i] += __shfl_down_sync(0xffffffffu, X[i], off);
            Y[i] += __shfl_down_sync(0xffffffffu, Y[i], off);
            Z[i] += __shfl_down_sync(0xffffffffu, Z[i], off);
        }
    }
    float* red = (float*)xbuf;
    int w = tid >> 5;
    if (lane == 0) {
        #pragma unroll
        for (int i = 0; i < 10; ++i) {
            red[w*30 + i]      = X[i];
            red[w*30 + 10 + i] = Y[i];
            red[w*30 + 20 + i] = Z[i];
        }
    }
    __syncthreads();
    if (tid < 30)
        g_expart[c*30 + tid] = red[tid] + red[30 + tid] + red[60 + tid] + red[90 + tid];
}

// ---------------------------------------------------------- select phase ----
__device__ void sel_phase(int c, int tid, int lane, u64* xbuf,
                          const float2* __restrict__ sang, const float2* sv0,
                          int nlayers, int adjoint, int init, int store, int doExp)
{
    Xch X{xbuf, 0, tid};
    u64 v[8];
    u64* gb = G_STATEU + ((size_t)c << 10);
    int base = (tid >> 5) * 256 + lane;
    if (init) {
        #pragma unroll
        for (int q = 0; q < 8; ++q) v[q] = 0ull;
        if (tid == 0) { float2 f = sv0[c & 15]; v[0] = pk2(f.x, f.y); }
    } else {
        #pragma unroll
        for (int q = 0; q < 8; ++q) v[q] = gb[base + q*32];
    }

    if (!adjoint) {
        const float sgn = 1.f;
        #pragma unroll 1
        for (int l = 0; l < nlayers; ++l) {
            const float2* a = sang + 40*l;
            ry_all(v, X, a, sgn, lane);
            ring_a(v, X, a + 10, sgn, lane, tid, false);
            ry_all(v, X, a + 20, sgn, lane);
            ring_b(v, X, a + 30, sgn, lane, tid, false);
        }
    } else {
        const float sgn = -1.f;
        #pragma unroll 1
        for (int l = nlayers - 1; l >= 0; --l) {
            const float2* a = sang + 40*l;
            ring_b(v, X, a + 30, sgn, lane, tid, true);
            ry_all(v, X, a + 20, sgn, lane);
            ring_a(v, X, a + 10, sgn, lane, tid, true);
            ry_all(v, X, a, sgn, lane);
        }
    }

    if (store) {
        #pragma unroll
        for (int q = 0; q < 8; ++q) gb[base + q*32] = v[q];
    }
    if (doExp) exp_partial(c, tid, lane, v, xbuf);
}

// ------------------------------------------------------------- anc phase ----
__device__ void anc_phase(int c, int tid, int mi, u64* pool)
{
    u64* tile = pool;
    u64* sM   = pool + 1024;
    int b = c >> 4, sc = c & 15;
    sM[tid]       = ((const u64*)g_M[mi])[tid];
    sM[128 + tid] = ((const u64*)g_M[mi])[128 + tid];
    size_t sb = ((size_t)b << 14) + ((size_t)sc << 6);
    #pragma unroll
    for (int i = 0; i < 8; ++i) {
        int idx = i*128 + tid;
        int a = idx >> 6, sj = idx & 63;
        tile[idx] = G_STATEU[sb + ((size_t)a << 10) + sj];
    }
    __syncthreads();
    #pragma unroll
    for (int i = 0; i < 8; ++i) {
        int idx = i*128 + tid;
        int a = idx >> 6, sj = idx & 63;
        u64 acc = 0ull;
        #pragma unroll
        for (int k = 0; k < 16; ++k) {
            float2 m = upk(sM[a*16 + k]);
            u64 xv = tile[k*64 + sj];
            acc = fma2(pk2(m.x, m.x), xv, acc);
            acc = fma2(pk2(-m.y, m.y), swap2(xv), acc);
        }
        G_STATEU[sb + ((size_t)a << 10) + sj] = acc;
    }
}

// -------------------------------------------------------------- mega --------
__global__ void __launch_bounds__(128, 2) mega(
    const float* __restrict__ x,
    const float* __restrict__ Wfp,
    const float* __restrict__ bfp,
    const float* __restrict__ prep_p,
    const float* __restrict__ sig_ang,
    const float* __restrict__ qff_p,
    const float* __restrict__ W_out,
    const float* __restrict__ b_out,
    float* __restrict__ out)
{
    int c = blockIdx.x;
    int bb = c >> 4;
    int cb = c & 15;
    int tid = threadIdx.x;
    int lane = tid & 31;
    __shared__ u64 xbuf[4096];
    __shared__ float2 sang[80];
    __shared__ float2 sqff[40];
    __shared__ float2 sv0[16];
    __shared__ unsigned s_base;
    if (tid == 0) s_base = *(volatile unsigned*)&g_bsns[bb];
    __syncthreads();
    unsigned gen = s_base;

    // ----- P0: local angles, local v0, leader publishes g_M. No batch bar. --
    {
        float* h = (float*)xbuf;
        if (tid < 64) {
            int f = tid;
            int k = f >> 1;
            float div = expf((float)(2*k) * (-logf(10000.0f) / 64.0f));
            float arg = (float)cb * div;
            float pe = (f & 1) ? cosf(arg) : sinf(arg);
            h[f] = x[(bb*64 + f)*16 + cb] + pe;
        }
        __syncthreads();
        if (tid < NROTS) {
            float acc = bfp[tid];
            const float* w = Wfp + tid*64;
            #pragma unroll
            for (int f = 0; f < 64; ++f) acc += h[f]*w[f];
            float sg = 1.0f / (1.0f + expf(-acc));
            float sn, cs;
            sincosf(3.14159265358979323846f * sg, &sn, &cs);
            sang[tid] = make_float2(cs, sn);
        }
        if (tid >= 88 && tid < 88 + QROTS) {
            float cq, sq;
            sincosf(0.5f * qff_p[tid - 88], &sq, &cq);
            sqff[tid - 88] = make_float2(cq, sq);
        }
        __syncthreads();
        float2 (*sU)[16] = (float2(*)[16])(xbuf + 64);
        if (tid < 16) {
            float2 v[16];
            #pragma unroll
            for (int i = 0; i < 16; ++i) v[i] = make_float2(0.f, 0.f);
            v[tid] = make_float2(1.f, 0.f);
            for (int ly = 0; ly < 4; ++ly) {
                for (int qi = 0; qi < 4; ++qi) {
                    int p = 3 - qi;
                    float thy = prep_p[(ly*4 + qi)*2 + 0];
                    float thz = prep_p[(ly*4 + qi)*2 + 1];
                    float cth, sth;
                    sincosf(0.5f*thy, &sth, &cth);
                    for (int m = 0; m < 8; ++m) {
                        int i0 = ((m >> p) << (p+1)) | (m & ((1 << p) - 1));
                        int i1 = i0 | (1 << p);
                        float2 a0 = v[i0], a1 = v[i1];
                        v[i0] = make_float2(cth*a0.x - sth*a1.x, cth*a0.y - sth*a1.y);
                        v[i1] = make_float2(sth*a0.x + cth*a1.x, sth*a0.y + cth*a1.y);
                    }
                    float cz, sz;
                    sincosf(0.5f*thz, &sz, &cz);
                    for (int i = 0; i < 16; ++i) {
                        float im = ((i >> p) & 1) ? sz : -sz;
                        float2 a = v[i];
                        v[i] = make_float2(cz*a.x - im*a.y, cz*a.y + im*a.x);
                    }
                }
                for (int i = 0; i < 3; ++i) {
                    int pc = 3 - i, pt = 2 - i;
                    for (int idx = 0; idx < 16; ++idx) {
                        if (((idx >> pc) & 1) == 1 && ((idx >> pt) & 1) == 0) {
                            int j = idx | (1 << pt);
                            float2 tmp = v[idx]; v[idx] = v[j]; v[j] = tmp;
                        }
                    }
                }
            }
            #pragma unroll
            for (int r = 0; r < 16; ++r) sU[r][tid] = v[r];
        }
        __syncthreads();
        if (tid < 16) {
            float c0, s0;
            sincosf(sig_ang[0], &s0, &c0);
            float2 u = sU[tid][0];
            sv0[tid] = make_float2(c0*u.x - s0*u.y, c0*u.y + s0*u.x);
        }
        if (cb == 0) {
            #pragma unroll 1
            for (int half = 0; half < 2; ++half) {
                int idx = half*128 + tid;
                int j = idx >> 4, k = idx & 15;
                for (int m = 0; m < 2; ++m) {
                    float cp, sp;
                    sincosf(sig_ang[m+1], &sp, &cp);
                    float2 acc = make_float2(0.f, 0.f);
                    #pragma unroll
                    for (int a = 0; a < 16; ++a) {
                        float2 uja = sU[j][a];
                        float2 uka = sU[k][a];
                        float dr = cp, di = (a == 0) ? sp : -sp;
                        float2 dc = make_float2(dr*uka.x + di*uka.y, di*uka.x - dr*uka.y);
                        acc.x += uja.x*dc.x - uja.y*dc.y;
                        acc.y += uja.x*dc.y + uja.y*dc.x;
                    }
                    g_M[m][j*16 + k] = acc;
                }
                float cp, sp;
                sincosf(sig_ang[3], &sp, &cp);
                float dr = cp, di = (j == 0) ? sp : -sp;
                float2 u2 = sU[k][j];
                g_M[2][j*16 + k] = make_float2(dr*u2.x + di*u2.y, di*u2.x - dr*u2.y);
            }
        }
        __syncthreads();
    }

    sel_phase(c, tid, lane, xbuf, sang, sv0, 2, 0, 1, 1, 0);   // k=0 fwd (init)
    bbar(bb, gen + 1);
    anc_phase(c, tid, 0, xbuf);
    bbar(bb, gen + 2);
    sel_phase(c, tid, lane, xbuf, sang, sv0, 2, 1, 0, 1, 0);   // k=1 adjoint
    bbar(bb, gen + 3);
    anc_phase(c, tid, 1, xbuf);
    bbar(bb, gen + 4);
    sel_phase(c, tid, lane, xbuf, sang, sv0, 2, 0, 0, 1, 0);   // k=2 fwd
    bbar(bb, gen + 5);
    anc_phase(c, tid, 2, xbuf);
    bbar(bb, gen + 6);
    sel_phase(c, tid, lane, xbuf, sqff, sv0, 1, 0, 0, 0, 1);   // qff + expvals
    bbar(bb, gen + 7);

    if (cb == 0) {
        float* exf = (float*)sang;
        if (tid < 30) {
            float s = 0.f;
            #pragma unroll
            for (int j = 0; j < 16; ++j) s += g_expart[(bb*16 + j)*30 + tid];
            exf[tid] = s;
        }
        __syncthreads();
        if (tid < ODIM) {
            float acc = b_out[tid];
            #pragma unroll
            for (int j = 0; j < 30; ++j) acc += W_out[tid*30 + j] * exf[j];
            out[bb*ODIM + tid] = acc;
        }
    }
}

// ------------------------------------------------------------ launch --------
extern "C" void kernel_launch(void* const* d_in, const int* in_sizes, int n_in,
                              void* d_out, int out_size)
{
    const float* x       = (const float*)d_in[0];
    const float* W_fp    = (const float*)d_in[1];
    const float* b_fp    = (const float*)d_in[2];
    const float* prep_p  = (const float*)d_in[3];
    const float* sig_ang = (const float*)d_in[4];
    const float* qff_p   = (const float*)d_in[5];
    const float* W_out   = (const float*)d_in[6];
    const float* b_out   = (const float*)d_in[7];
    float* out = (float*)d_out;

    mega<<<NCTA, 128>>>(x, W_fp, b_fp, prep_p, sig_ang, qff_p, W_out, b_out, out);
}

// round 16
// speedup vs baseline: 1.1393x; 1.1393x over previous
#include <cuda_runtime.h>
#include <math.h>

#define Bsz 16
#define Tn 16
#define FDIM 64
#define ODIM 8
#define NQ 10
#define NA 4
#define NROTS 80
#define QROTS 40
#define NS 1024
#define NANC 16
#define STATE_PER_B (NS*NANC)
#define TOTAL_AMPS (Bsz*STATE_PER_B)
#define NCTA 256

typedef unsigned long long u64;

__device__ float4 g_state4[TOTAL_AMPS/2];
#define G_STATE  ((float2*)g_state4)
#define G_STATEU ((u64*)g_state4)
__device__ float2 g_M[2][256];
__device__ float  g_expart[NCTA*30];
__device__ unsigned g_bcnt[16];
__device__ unsigned g_bsns[16];

// ------------------------------------------------------- packed f32x2 ops ---
__device__ __forceinline__ u64 pk2(float x, float y) {
    u64 r; asm("mov.b64 %0, {%1, %2};" : "=l"(r) : "f"(x), "f"(y)); return r;
}
__device__ __forceinline__ float2 upk(u64 a) {
    float2 f; asm("mov.b64 {%0, %1}, %2;" : "=f"(f.x), "=f"(f.y) : "l"(a)); return f;
}
__device__ __forceinline__ u64 mul2(u64 a, u64 b) {
    u64 d; asm("mul.rn.f32x2 %0, %1, %2;" : "=l"(d) : "l"(a), "l"(b)); return d;
}
__device__ __forceinline__ u64 fma2(u64 a, u64 b, u64 c) {
    u64 d; asm("fma.rn.f32x2 %0, %1, %2, %3;" : "=l"(d) : "l"(a), "l"(b), "l"(c)); return d;
}
__device__ __forceinline__ u64 swap2(u64 a) {
    float2 f = upk(a); return pk2(f.y, f.x);
}

// ----------------------------------------------------- per-batch barrier ----
__device__ __forceinline__ void bbar(int b, unsigned target)
{
    __syncthreads();
    if (threadIdx.x == 0) {
        __threadfence();
        unsigned arrived = atomicAdd(&g_bcnt[b], 1u) + 1u;
        if (arrived == 16u) {
            g_bcnt[b] = 0u;
            __threadfence();
            atomicExch(&g_bsns[b], target);
        } else {
            while ((int)(*(volatile unsigned*)&g_bsns[b] - target) < 0) { }
        }
        __threadfence();
    }
    __syncthreads();
}

// ------------------------------------------------------- gate primitives ----
// layout: amplitude s: lane = s[4:0], reg = s[7:5] (8 u64/lane), warp = s[9:8].

template<int PB>
__device__ __forceinline__ void ry_reg(u64* v, float cc, float ss)
{
    u64 cc2 = pk2(cc, cc), ss2 = pk2(ss, ss), nss2 = pk2(-ss, -ss);
    #pragma unroll
    for (int m = 0; m < 4; ++m) {
        int i0 = ((m >> PB) << (PB+1)) | (m & ((1 << PB) - 1));
        int i1 = i0 | (1 << PB);
        u64 a0 = v[i0], a1 = v[i1];
        v[i0] = fma2(cc2, a0, mul2(nss2, a1));
        v[i1] = fma2(cc2, a1, mul2(ss2, a0));
    }
}

__device__ __forceinline__ void ry_lane(u64* v, int pl, float cc, float ss, int lane)
{
    float sg = ((lane >> pl) & 1) ? ss : -ss;
    u64 cc2 = pk2(cc, cc), sg2 = pk2(sg, sg);
    int mk = 1 << pl;
    #pragma unroll
    for (int q = 0; q < 8; ++q) {
        float2 f = upk(v[q]);
        float px = __shfl_xor_sync(0xffffffffu, f.x, mk);
        float py = __shfl_xor_sync(0xffffffffu, f.y, mk);
        v[q] = fma2(cc2, v[q], mul2(sg2, pk2(px, py)));
    }
}

template<int PCB, int PTB>
__device__ __forceinline__ void crx_rr(u64* v, float cc, float ss)
{
    u64 cc2 = pk2(cc, cc), ssv2 = pk2(ss, -ss);
    #pragma unroll
    for (int i = 0; i < 8; ++i) {
        if ((((i >> PCB) & 1) == 1) && (((i >> PTB) & 1) == 0)) {
            int i1 = i | (1 << PTB);
            u64 a0 = v[i], a1 = v[i1];
            v[i]  = fma2(cc2, a0, mul2(ssv2, swap2(a1)));
            v[i1] = fma2(cc2, a1, mul2(ssv2, swap2(a0)));
        }
    }
}

__device__ __forceinline__ void crx_shfl(u64* v, int pt, bool act, float cc, float ss)
{
    float ccl = act ? cc : 1.f, ssl = act ? ss : 0.f;
    u64 cc2 = pk2(ccl, ccl), ssv2 = pk2(ssl, -ssl);
    int mk = 1 << pt;
    #pragma unroll
    for (int q = 0; q < 8; ++q) {
        float2 f = upk(v[q]);
        float px = __shfl_xor_sync(0xffffffffu, f.x, mk);
        float py = __shfl_xor_sync(0xffffffffu, f.y, mk);
        v[q] = fma2(cc2, v[q], mul2(ssv2, pk2(py, px)));
    }
}

template<int PCB>
__device__ __forceinline__ void crx_rl(u64* v, int pt, float cc, float ss)
{
    u64 cc2 = pk2(cc, cc), ssv2 = pk2(ss, -ss);
    int mk = 1 << pt;
    #pragma unroll
    for (int q = 0; q < 8; ++q) {
        if ((q >> PCB) & 1) {
            float2 f = upk(v[q]);
            float px = __shfl_xor_sync(0xffffffffu, f.x, mk);
            float py = __shfl_xor_sync(0xffffffffu, f.y, mk);
            v[q] = fma2(cc2, v[q], mul2(ssv2, pk2(py, px)));
        }
    }
}

template<int PTB>
__device__ __forceinline__ void crx_reg_tgt(u64* v, bool act, float cc, float ss)
{
    float ccl = act ? cc : 1.f, ssl = act ? ss : 0.f;
    u64 cc2 = pk2(ccl, ccl), ssv2 = pk2(ssl, -ssl);
    #pragma unroll
    for (int m = 0; m < 4; ++m) {
        int i0 = ((m >> PTB) << (PTB+1)) | (m & ((1 << PTB) - 1));
        int i1 = i0 | (1 << PTB);
        u64 a0 = v[i0], a1 = v[i1];
        v[i0] = fma2(cc2, a0, mul2(ssv2, swap2(a1)));
        v[i1] = fma2(cc2, a1, mul2(ssv2, swap2(a0)));
    }
}

// ----- cross-warp exchange gates (double-buffered smem, 1 CTA bar each) -----
struct Xch {
    u64* base; int tog; int tid;
    __device__ __forceinline__ u64* next() { u64* p = base + ((tog & 1) << 10); ++tog; return p; }
};

__device__ __forceinline__ void ry_warp(u64* v, Xch& X, int wb, float cc, float ss)
{
    u64* b = X.next();
    int tid = X.tid, xv = 32 << wb;
    #pragma unroll
    for (int i = 0; i < 8; ++i) b[i*128 + tid] = v[i];
    __syncthreads();
    float sg = ((tid >> (5 + wb)) & 1) ? ss : -ss;
    u64 cc2 = pk2(cc, cc), sg2 = pk2(sg, sg);
    #pragma unroll
    for (int i = 0; i < 8; ++i)
        v[i] = fma2(cc2, v[i], mul2(sg2, b[i*128 + (tid ^ xv)]));
}

__device__ __forceinline__ void crx_warp_tgt(u64* v, Xch& X, int twb, bool act, float cc, float ss)
{
    u64* b = X.next();
    int tid = X.tid, xv = 32 << twb;
    #pragma unroll
    for (int i = 0; i < 8; ++i) b[i*128 + tid] = v[i];
    __syncthreads();
    float ccl = act ? cc : 1.f, ssl = act ? ss : 0.f;
    u64 cc2 = pk2(ccl, ccl), ssv2 = pk2(ssl, -ssl);
    #pragma unroll
    for (int i = 0; i < 8; ++i)
        v[i] = fma2(cc2, v[i], mul2(ssv2, swap2(b[i*128 + (tid ^ xv)])));
}

__device__ __forceinline__ void crx_rw(u64* v, Xch& X, int twb, float cc, float ss)
{
    u64* b = X.next();
    int tid = X.tid, xv = 32 << twb;
    #pragma unroll
    for (int i = 0; i < 4; ++i) b[i*128 + tid] = v[4 + i];
    __syncthreads();
    u64 cc2 = pk2(cc, cc), ssv2 = pk2(ss, -ss);
    #pragma unroll
    for (int i = 0; i < 4; ++i)
        v[4 + i] = fma2(cc2, v[4 + i], mul2(ssv2, swap2(b[i*128 + (tid ^ xv)])));
}

// -------------------------------------------------------- layer pieces ------
#define SS(A) (sgn*(A).y)

__device__ __forceinline__ void ry_all(u64* v, Xch& X, const float2* __restrict__ ang,
                                       float sgn, int lane)
{
    ry_warp(v, X, 1, ang[0].x, SS(ang[0]));
    ry_warp(v, X, 0, ang[1].x, SS(ang[1]));
    ry_reg<2>(v, ang[2].x, SS(ang[2]));
    ry_reg<1>(v, ang[3].x, SS(ang[3]));
    ry_reg<0>(v, ang[4].x, SS(ang[4]));
    #pragma unroll 1
    for (int pl = 4; pl >= 0; --pl) {
        float2 cs = ang[9 - pl];
        ry_lane(v, pl, cs.x, sgn*cs.y, lane);
    }
}

__device__ __forceinline__ void ring_a(u64* v, Xch& X, const float2* __restrict__ ang,
                                       float sgn, int lane, int tid, bool rev)
{
    if (!rev) {
        crx_warp_tgt(v, X, 1, lane & 1, ang[0].x, SS(ang[0]));
        crx_shfl(v, 0, (lane >> 1) & 1, ang[1].x, SS(ang[1]));
        crx_shfl(v, 1, (lane >> 2) & 1, ang[2].x, SS(ang[2]));
        crx_shfl(v, 2, (lane >> 3) & 1, ang[3].x, SS(ang[3]));
        crx_shfl(v, 3, (lane >> 4) & 1, ang[4].x, SS(ang[4]));
        crx_rl<0>(v, 4, ang[5].x, SS(ang[5]));
        crx_rr<1,0>(v, ang[6].x, SS(ang[6]));
        crx_rr<2,1>(v, ang[7].x, SS(ang[7]));
        crx_reg_tgt<2>(v, (tid >> 5) & 1, ang[8].x, SS(ang[8]));
        crx_warp_tgt(v, X, 0, (tid >> 6) & 1, ang[9].x, SS(ang[9]));
    } else {
        crx_warp_tgt(v, X, 0, (tid >> 6) & 1, ang[9].x, SS(ang[9]));
        crx_reg_tgt<2>(v, (tid >> 5) & 1, ang[8].x, SS(ang[8]));
        crx_rr<2,1>(v, ang[7].x, SS(ang[7]));
        crx_rr<1,0>(v, ang[6].x, SS(ang[6]));
        crx_rl<0>(v, 4, ang[5].x, SS(ang[5]));
        crx_shfl(v, 3, (lane >> 4) & 1, ang[4].x, SS(ang[4]));
        crx_shfl(v, 2, (lane >> 3) & 1, ang[3].x, SS(ang[3]));
        crx_shfl(v, 1, (lane >> 2) & 1, ang[2].x, SS(ang[2]));
        crx_shfl(v, 0, (lane >> 1) & 1, ang[1].x, SS(ang[1]));
        crx_warp_tgt(v, X, 1, lane & 1, ang[0].x, SS(ang[0]));
    }
}

__device__ __forceinline__ void ring_b(u64* v, Xch& X, const float2* __restrict__ ang,
                                       float sgn, int lane, int tid, bool rev)
{
    if (!rev) {
        crx_shfl(v, 1, lane & 1, ang[0].x, SS(ang[0]));
        crx_shfl(v, 0, (tid >> 6) & 1, ang[1].x, SS(ang[1]));
        crx_warp_tgt(v, X, 1, (tid >> 5) & 1, ang[2].x, SS(ang[2]));
        crx_rw(v, X, 0, ang[3].x, SS(ang[3]));
        crx_rr<1,2>(v, ang[4].x, SS(ang[4]));
        crx_rr<0,1>(v, ang[5].x, SS(ang[5]));
        crx_reg_tgt<0>(v, (lane >> 4) & 1, ang[6].x, SS(ang[6]));
        crx_shfl(v, 4, (lane >> 3) & 1, ang[7].x, SS(ang[7]));
        crx_shfl(v, 3, (lane >> 2) & 1, ang[8].x, SS(ang[8]));
        crx_shfl(v, 2, (lane >> 1) & 1, ang[9].x, SS(ang[9]));
    } else {
        crx_shfl(v, 2, (lane >> 1) & 1, ang[9].x, SS(ang[9]));
        crx_shfl(v, 3, (lane >> 2) & 1, ang[8].x, SS(ang[8]));
        crx_shfl(v, 4, (lane >> 3) & 1, ang[7].x, SS(ang[7]));
        crx_reg_tgt<0>(v, (lane >> 4) & 1, ang[6].x, SS(ang[6]));
        crx_rr<0,1>(v, ang[5].x, SS(ang[5]));
        crx_rr<1,2>(v, ang[4].x, SS(ang[4]));
        crx_rw(v, X, 0, ang[3].x, SS(ang[3]));
        crx_warp_tgt(v, X, 1, (tid >> 5) & 1, ang[2].x, SS(ang[2]));
        crx_shfl(v, 0, (tid >> 6) & 1, ang[1].x, SS(ang[1]));
        crx_shfl(v, 1, lane & 1, ang[0].x, SS(ang[0]));
    }
}

// --------------------------------------------------- in-register expvals ----
__device__ void exp_partial(int c, int tid, int lane, u64* v, u64* xbuf)
{
    __syncthreads();   // ensure no warp still reads exchange buffers
    float X[10], Y[10], Z[10];
    #pragma unroll
    for (int i = 0; i < 10; ++i) { X[i] = 0.f; Y[i] = 0.f; Z[i] = 0.f; }

    #pragma unroll
    for (int p = 0; p < 5; ++p) {
        int i = 9 - p;
        int mk = 1 << p;
        float sg = ((lane >> p) & 1) ? -1.f : 1.f;
        #pragma unroll
        for (int q = 0; q < 8; ++q) {
            float2 f = upk(v[q]);
            float px = __shfl_xor_sync(0xffffffffu, f.x, mk);
            float py = __shfl_xor_sync(0xffffffffu, f.y, mk);
            X[i] += f.x*px + f.y*py;
            Y[i] += sg*(f.x*py - f.y*px);
            Z[i] += sg*(f.x*f.x + f.y*f.y);
        }
    }
    #pragma unroll
    for (int pb = 0; pb < 3; ++pb) {
        int i = 4 - pb;
        #pragma unroll
        for (int m = 0; m < 4; ++m) {
            int i0 = ((m >> pb) << (pb+1)) | (m & ((1 << pb) - 1));
            int i1 = i0 | (1 << pb);
            float2 a = upk(v[i0]), cc = upk(v[i1]);
            X[i] += 2.f*(a.x*cc.x + a.y*cc.y);
            Y[i] += 2.f*(a.x*cc.y - a.y*cc.x);
            Z[i] += (a.x*a.x + a.y*a.y) - (cc.x*cc.x + cc.y*cc.y);
        }
    }
    #pragma unroll
    for (int q = 0; q < 8; ++q) xbuf[q*128 + tid] = v[q];
    __syncthreads();
    #pragma unroll
    for (int wb = 0; wb < 2; ++wb) {
        int i = 1 - wb;
        int pr = tid ^ (32 << wb);
        float sg = ((tid >> (5 + wb)) & 1) ? -1.f : 1.f;
        #pragma unroll
        for (int q = 0; q < 8; ++q) {
            float2 g = upk(xbuf[q*128 + pr]);
            float2 f = upk(v[q]);
            X[i] += f.x*g.x + f.y*g.y;
            Y[i] += sg*(f.x*g.y - f.y*g.x);
            Z[i] += sg*(f.x*f.x + f.y*f.y);
        }
    }
    __syncthreads();
    #pragma unroll
    for (int i = 0; i < 10; ++i) {
        #pragma unroll
        for (int off = 16; off; off >>= 1) {
            X[i] += __shfl_down_sync(0xffffffffu, X[i], off);
            Y[i] += __shfl_down_sync(0xffffffffu, Y[i], off);
            Z[i] += __shfl_down_sync(0xffffffffu, Z[i], off);
        }
    }
    float* red = (float*)xbuf;
    int w = tid >> 5;
    if (lane == 0) {
        #pragma unroll
        for (int i = 0; i < 10; ++i) {
            red[w*30 + i]      = X[i];
            red[w*30 + 10 + i] = Y[i];
            red[w*30 + 20 + i] = Z[i];
        }
    }
    __syncthreads();
    if (tid < 30)
        g_expart[c*30 + tid] = red[tid] + red[30 + tid] + red[60 + tid] + red[90 + tid];
}

// ---------------------------------------------------------- select phase ----
__device__ void sel_phase(int c, int tid, int lane, u64* xbuf,
                          const float2* __restrict__ sang, const float2* sv0,
                          int adjoint, int init)
{
    Xch X{xbuf, 0, tid};
    u64 v[8];
    u64* gb = G_STATEU + ((size_t)c << 10);
    int base = (tid >> 5) * 256 + lane;
    if (init) {
        #pragma unroll
        for (int q = 0; q < 8; ++q) v[q] = 0ull;
        if (tid == 0) { float2 f = sv0[c & 15]; v[0] = pk2(f.x, f.y); }
    } else {
        #pragma unroll
        for (int q = 0; q < 8; ++q) v[q] = gb[base + q*32];
    }

    if (!adjoint) {
        const float sgn = 1.f;
        #pragma unroll 1
        for (int l = 0; l < 2; ++l) {
            const float2* a = sang + 40*l;
            ry_all(v, X, a, sgn, lane);
            ring_a(v, X, a + 10, sgn, lane, tid, false);
            ry_all(v, X, a + 20, sgn, lane);
            ring_b(v, X, a + 30, sgn, lane, tid, false);
        }
    } else {
        const float sgn = -1.f;
        #pragma unroll 1
        for (int l = 1; l >= 0; --l) {
            const float2* a = sang + 40*l;
            ring_b(v, X, a + 30, sgn, lane, tid, true);
            ry_all(v, X, a + 20, sgn, lane);
            ring_a(v, X, a + 10, sgn, lane, tid, true);
            ry_all(v, X, a, sgn, lane);
        }
    }

    #pragma unroll
    for (int q = 0; q < 8; ++q) gb[base + q*32] = v[q];
}

// ----- tail: select fwd (2 layers) + qff layer + expvals, register-resident --
__device__ void sel_tail(int c, int tid, int lane, u64* xbuf,
                         const float2* __restrict__ sang,
                         const float2* __restrict__ sqff)
{
    Xch X{xbuf, 0, tid};
    u64 v[8];
    u64* gb = G_STATEU + ((size_t)c << 10);
    int base = (tid >> 5) * 256 + lane;
    #pragma unroll
    for (int q = 0; q < 8; ++q) v[q] = gb[base + q*32];

    const float sgn = 1.f;
    #pragma unroll 1
    for (int l = 0; l < 2; ++l) {
        const float2* a = sang + 40*l;
        ry_all(v, X, a, sgn, lane);
        ring_a(v, X, a + 10, sgn, lane, tid, false);
        ry_all(v, X, a + 20, sgn, lane);
        ring_b(v, X, a + 30, sgn, lane, tid, false);
    }
    // qff layer (F = D3*U^T dropped: unitary on ancilla, commutes w/ qff & obs)
    ry_all(v, X, sqff, sgn, lane);
    ring_a(v, X, sqff + 10, sgn, lane, tid, false);
    ry_all(v, X, sqff + 20, sgn, lane);
    ring_b(v, X, sqff + 30, sgn, lane, tid, false);

    exp_partial(c, tid, lane, v, xbuf);
}

// ------------------------------------------------------------- anc phase ----
__device__ void anc_phase(int c, int tid, int mi, u64* pool)
{
    u64* tile = pool;
    u64* sM   = pool + 1024;
    int b = c >> 4, sc = c & 15;
    sM[tid]       = ((const u64*)g_M[mi])[tid];
    sM[128 + tid] = ((const u64*)g_M[mi])[128 + tid];
    size_t sb = ((size_t)b << 14) + ((size_t)sc << 6);
    #pragma unroll
    for (int i = 0; i < 8; ++i) {
        int idx = i*128 + tid;
        int a = idx >> 6, sj = idx & 63;
        tile[idx] = G_STATEU[sb + ((size_t)a << 10) + sj];
    }
    __syncthreads();
    #pragma unroll
    for (int i = 0; i < 8; ++i) {
        int idx = i*128 + tid;
        int a = idx >> 6, sj = idx & 63;
        u64 acc = 0ull;
        #pragma unroll
        for (int k = 0; k < 16; ++k) {
            float2 m = upk(sM[a*16 + k]);
            u64 xv = tile[k*64 + sj];
            acc = fma2(pk2(m.x, m.x), xv, acc);
            acc = fma2(pk2(-m.y, m.y), swap2(xv), acc);
        }
        G_STATEU[sb + ((size_t)a << 10) + sj] = acc;
    }
}

// -------------------------------------------------------------- mega --------
__global__ void __launch_bounds__(128, 2) mega(
    const float* __restrict__ x,
    const float* __restrict__ Wfp,
    const float* __restrict__ bfp,
    const float* __restrict__ prep_p,
    const float* __restrict__ sig_ang,
    const float* __restrict__ qff_p,
    const float* __restrict__ W_out,
    const float* __restrict__ b_out,
    float* __restrict__ out)
{
    int c = blockIdx.x;
    int bb = c >> 4;
    int cb = c & 15;
    int tid = threadIdx.x;
    int lane = tid & 31;
    __shared__ u64 xbuf[2048];
    __shared__ float2 sang[80];
    __shared__ float2 sqff[40];
    __shared__ float2 sv0[16];
    __shared__ unsigned s_base;
    if (tid == 0) s_base = *(volatile unsigned*)&g_bsns[bb];
    __syncthreads();
    unsigned gen = s_base;

    // ----- P0: local angles, local v0, leader publishes g_M. No batch bar. --
    {
        float* h = (float*)xbuf;
        if (tid < 64) {
            int f = tid;
            int k = f >> 1;
            float div = expf((float)(2*k) * (-logf(10000.0f) / 64.0f));
            float arg = (float)cb * div;
            float pe = (f & 1) ? cosf(arg) : sinf(arg);
            h[f] = x[(bb*64 + f)*16 + cb] + pe;
        }
        __syncthreads();
        if (tid < NROTS) {
            float acc = bfp[tid];
            const float* w = Wfp + tid*64;
            #pragma unroll
            for (int f = 0; f < 64; ++f) acc += h[f]*w[f];
            float sg = 1.0f / (1.0f + expf(-acc));
            float sn, cs;
            sincosf(3.14159265358979323846f * sg, &sn, &cs);
            sang[tid] = make_float2(cs, sn);
        }
        if (tid >= 88 && tid < 88 + QROTS) {
            float cq, sq;
            sincosf(0.5f * qff_p[tid - 88], &sq, &cq);
            sqff[tid - 88] = make_float2(cq, sq);
        }
        __syncthreads();
        float2 (*sU)[16] = (float2(*)[16])(xbuf + 64);
        if (tid < 16) {
            float2 v[16];
            #pragma unroll
            for (int i = 0; i < 16; ++i) v[i] = make_float2(0.f, 0.f);
            v[tid] = make_float2(1.f, 0.f);
            for (int ly = 0; ly < 4; ++ly) {
                for (int qi = 0; qi < 4; ++qi) {
                    int p = 3 - qi;
                    float thy = prep_p[(ly*4 + qi)*2 + 0];
                    float thz = prep_p[(ly*4 + qi)*2 + 1];
                    float cth, sth;
                    sincosf(0.5f*thy, &sth, &cth);
                    for (int m = 0; m < 8; ++m) {
                        int i0 = ((m >> p) << (p+1)) | (m & ((1 << p) - 1));
                        int i1 = i0 | (1 << p);
                        float2 a0 = v[i0], a1 = v[i1];
                        v[i0] = make_float2(cth*a0.x - sth*a1.x, cth*a0.y - sth*a1.y);
                        v[i1] = make_float2(sth*a0.x + cth*a1.x, sth*a0.y + cth*a1.y);
                    }
                    float cz, sz;
                    sincosf(0.5f*thz, &sz, &cz);
                    for (int i = 0; i < 16; ++i) {
                        float im = ((i >> p) & 1) ? sz : -sz;
                        float2 a = v[i];
                        v[i] = make_float2(cz*a.x - im*a.y, cz*a.y + im*a.x);
                    }
                }
                for (int i = 0; i < 3; ++i) {
                    int pc = 3 - i, pt = 2 - i;
                    for (int idx = 0; idx < 16; ++idx) {
                        if (((idx >> pc) & 1) == 1 && ((idx >> pt) & 1) == 0) {
                            int j = idx | (1 << pt);
                            float2 tmp = v[idx]; v[idx] = v[j]; v[j] = tmp;
                        }
                    }
                }
            }
            #pragma unroll
            for (int r = 0; r < 16; ++r) sU[r][tid] = v[r];
        }
        __syncthreads();
        if (tid < 16) {
            float c0, s0;
            sincosf(sig_ang[0], &s0, &c0);
            float2 u = sU[tid][0];
            sv0[tid] = make_float2(c0*u.x - s0*u.y, c0*u.y + s0*u.x);
        }
        if (cb == 0) {
            #pragma unroll 1
            for (int half = 0; half < 2; ++half) {
                int idx = half*128 + tid;
                int j = idx >> 4, k = idx & 15;
                for (int m = 0; m < 2; ++m) {
                    float cp, sp;
                    sincosf(sig_ang[m+1], &sp, &cp);
                    float2 acc = make_float2(0.f, 0.f);
                    #pragma unroll
                    for (int a = 0; a < 16; ++a) {
                        float2 uja = sU[j][a];
                        float2 uka = sU[k][a];
                        float dr = cp, di = (a == 0) ? sp : -sp;
                        float2 dc = make_float2(dr*uka.x + di*uka.y, di*uka.x - dr*uka.y);
                        acc.x += uja.x*dc.x - uja.y*dc.y;
                        acc.y += uja.x*dc.y + uja.y*dc.x;
                    }
                    g_M[m][j*16 + k] = acc;
                }
            }
        }
        __syncthreads();
    }

    sel_phase(c, tid, lane, xbuf, sang, sv0, 0, 1);   // k=0 fwd (init), store
    bbar(bb, gen + 1);
    anc_phase(c, tid, 0, xbuf);
    bbar(bb, gen + 2);
    sel_phase(c, tid, lane, xbuf, sang, sv0, 1, 0);   // k=1 adjoint, store
    bbar(bb, gen + 3);
    anc_phase(c, tid, 1, xbuf);
    bbar(bb, gen + 4);
    sel_tail(c, tid, lane, xbuf, sang, sqff);          // k=2 fwd + qff + exp
    bbar(bb, gen + 5);

    if (cb == 0) {
        float* exf = (float*)sang;
        if (tid < 30) {
            float s = 0.f;
            #pragma unroll
            for (int j = 0; j < 16; ++j) s += g_expart[(bb*16 + j)*30 + tid];
            exf[tid] = s;
        }
        __syncthreads();
        if (tid < ODIM) {
            float acc = b_out[tid];
            #pragma unroll
            for (int j = 0; j < 30; ++j) acc += W_out[tid*30 + j] * exf[j];
            out[bb*ODIM + tid] = acc;
        }
    }
}

// ------------------------------------------------------------ launch --------
extern "C" void kernel_launch(void* const* d_in, const int* in_sizes, int n_in,
                              void* d_out, int out_size)
{
    const float* x       = (const float*)d_in[0];
    const float* W_fp    = (const float*)d_in[1];
    const float* b_fp    = (const float*)d_in[2];
    const float* prep_p  = (const float*)d_in[3];
    const float* sig_ang = (const float*)d_in[4];
    const float* qff_p   = (const float*)d_in[5];
    const float* W_out   = (const float*)d_in[6];
    const float* b_out   = (const float*)d_in[7];
    float* out = (float*)d_out;

    mega<<<NCTA, 128>>>(x, W_fp, b_fp, prep_p, sig_ang, qff_p, W_out, b_out, out);
}

// round 17
// speedup vs baseline: 1.1834x; 1.0387x over previous
#include <cuda_runtime.h>
#include <math.h>

#define Bsz 16
#define Tn 16
#define FDIM 64
#define ODIM 8
#define NQ 10
#define NA 4
#define NROTS 80
#define QROTS 40
#define NS 1024
#define NANC 16
#define STATE_PER_B (NS*NANC)
#define TOTAL_AMPS (Bsz*STATE_PER_B)
#define NCTA 256

typedef unsigned long long u64;

__device__ float4 g_state4[TOTAL_AMPS/2];
#define G_STATE  ((float2*)g_state4)
#define G_STATEU ((u64*)g_state4)
__device__ float2 g_M[2][256];
__device__ float  g_expart[NCTA*30];
__device__ unsigned g_bcnt[16];
__device__ unsigned g_bsns[16];

// ------------------------------------------------------- packed f32x2 ops ---
__device__ __forceinline__ u64 pk2(float x, float y) {
    u64 r; asm("mov.b64 %0, {%1, %2};" : "=l"(r) : "f"(x), "f"(y)); return r;
}
__device__ __forceinline__ float2 upk(u64 a) {
    float2 f; asm("mov.b64 {%0, %1}, %2;" : "=f"(f.x), "=f"(f.y) : "l"(a)); return f;
}
__device__ __forceinline__ u64 mul2(u64 a, u64 b) {
    u64 d; asm("mul.rn.f32x2 %0, %1, %2;" : "=l"(d) : "l"(a), "l"(b)); return d;
}
__device__ __forceinline__ u64 fma2(u64 a, u64 b, u64 c) {
    u64 d; asm("fma.rn.f32x2 %0, %1, %2, %3;" : "=l"(d) : "l"(a), "l"(b), "l"(c)); return d;
}
__device__ __forceinline__ u64 swap2(u64 a) {
    float2 f = upk(a); return pk2(f.y, f.x);
}

// ----------------------------------------------------- per-batch barrier ----
__device__ __forceinline__ void bbar(int b, unsigned target)
{
    __syncthreads();
    if (threadIdx.x == 0) {
        __threadfence();
        unsigned arrived = atomicAdd(&g_bcnt[b], 1u) + 1u;
        if (arrived == 16u) {
            g_bcnt[b] = 0u;
            __threadfence();
            atomicExch(&g_bsns[b], target);
        } else {
            while ((int)(*(volatile unsigned*)&g_bsns[b] - target) < 0) { }
        }
        __threadfence();
    }
    __syncthreads();
}

// ------------------------------------------------------- gate primitives ----
// layout: amplitude s: lane = s[4:0], reg = s[7:5] (8 u64/lane), warp = s[9:8].

template<int PB>
__device__ __forceinline__ void ry_reg(u64* v, float cc, float ss)
{
    u64 cc2 = pk2(cc, cc), ss2 = pk2(ss, ss), nss2 = pk2(-ss, -ss);
    #pragma unroll
    for (int m = 0; m < 4; ++m) {
        int i0 = ((m >> PB) << (PB+1)) | (m & ((1 << PB) - 1));
        int i1 = i0 | (1 << PB);
        u64 a0 = v[i0], a1 = v[i1];
        v[i0] = fma2(cc2, a0, mul2(nss2, a1));
        v[i1] = fma2(cc2, a1, mul2(ss2, a0));
    }
}

__device__ __forceinline__ void ry_lane(u64* v, int pl, float cc, float ss, int lane)
{
    float sg = ((lane >> pl) & 1) ? ss : -ss;
    u64 cc2 = pk2(cc, cc), sg2 = pk2(sg, sg);
    int mk = 1 << pl;
    #pragma unroll
    for (int q = 0; q < 8; ++q) {
        float2 f = upk(v[q]);
        float px = __shfl_xor_sync(0xffffffffu, f.x, mk);
        float py = __shfl_xor_sync(0xffffffffu, f.y, mk);
        v[q] = fma2(cc2, v[q], mul2(sg2, pk2(px, py)));
    }
}

template<int PCB, int PTB>
__device__ __forceinline__ void crx_rr(u64* v, float cc, float ss)
{
    u64 cc2 = pk2(cc, cc), ssv2 = pk2(ss, -ss);
    #pragma unroll
    for (int i = 0; i < 8; ++i) {
        if ((((i >> PCB) & 1) == 1) && (((i >> PTB) & 1) == 0)) {
            int i1 = i | (1 << PTB);
            u64 a0 = v[i], a1 = v[i1];
            v[i]  = fma2(cc2, a0, mul2(ssv2, swap2(a1)));
            v[i1] = fma2(cc2, a1, mul2(ssv2, swap2(a0)));
        }
    }
}

__device__ __forceinline__ void crx_shfl(u64* v, int pt, bool act, float cc, float ss)
{
    float ccl = act ? cc : 1.f, ssl = act ? ss : 0.f;
    u64 cc2 = pk2(ccl, ccl), ssv2 = pk2(ssl, -ssl);
    int mk = 1 << pt;
    #pragma unroll
    for (int q = 0; q < 8; ++q) {
        float2 f = upk(v[q]);
        float px = __shfl_xor_sync(0xffffffffu, f.x, mk);
        float py = __shfl_xor_sync(0xffffffffu, f.y, mk);
        v[q] = fma2(cc2, v[q], mul2(ssv2, pk2(py, px)));
    }
}

template<int PCB>
__device__ __forceinline__ void crx_rl(u64* v, int pt, float cc, float ss)
{
    u64 cc2 = pk2(cc, cc), ssv2 = pk2(ss, -ss);
    int mk = 1 << pt;
    #pragma unroll
    for (int q = 0; q < 8; ++q) {
        if ((q >> PCB) & 1) {
            float2 f = upk(v[q]);
            float px = __shfl_xor_sync(0xffffffffu, f.x, mk);
            float py = __shfl_xor_sync(0xffffffffu, f.y, mk);
            v[q] = fma2(cc2, v[q], mul2(ssv2, pk2(py, px)));
        }
    }
}

template<int PTB>
__device__ __forceinline__ void crx_reg_tgt(u64* v, bool act, float cc, float ss)
{
    float ccl = act ? cc : 1.f, ssl = act ? ss : 0.f;
    u64 cc2 = pk2(ccl, ccl), ssv2 = pk2(ssl, -ssl);
    #pragma unroll
    for (int m = 0; m < 4; ++m) {
        int i0 = ((m >> PTB) << (PTB+1)) | (m & ((1 << PTB) - 1));
        int i1 = i0 | (1 << PTB);
        u64 a0 = v[i0], a1 = v[i1];
        v[i0] = fma2(cc2, a0, mul2(ssv2, swap2(a1)));
        v[i1] = fma2(cc2, a1, mul2(ssv2, swap2(a0)));
    }
}

// ----- cross-warp exchange gates (double-buffered smem, 1 CTA bar each) -----
struct Xch {
    u64* base; int tog; int tid;
    __device__ __forceinline__ u64* next() { u64* p = base + ((tog & 1) << 10); ++tog; return p; }
};

// merged RY(bit9, angle0) * RY(bit8, angle1): one exchange, 4-term update.
// RYq0 and RYq1 commute, so the same block (with negated sines) is its adjoint.
__device__ __forceinline__ void ry2_warp(u64* v, Xch& X,
                                         float cc0, float ss0, float cc1, float ss1)
{
    u64* b = X.next();
    int tid = X.tid;
    #pragma unroll
    for (int i = 0; i < 8; ++i) b[i*128 + tid] = v[i];
    __syncthreads();
    float f9 = ((tid >> 6) & 1) ? ss0 : -ss0;   // bit9 coeff (dest-bit sign)
    float f8 = ((tid >> 5) & 1) ? ss1 : -ss1;   // bit8 coeff
    u64 k00 = pk2(cc0*cc1, cc0*cc1);
    u64 k01 = pk2(cc0*f8, cc0*f8);
    u64 k10 = pk2(f9*cc1, f9*cc1);
    u64 k11 = pk2(f9*f8, f9*f8);
    #pragma unroll
    for (int i = 0; i < 8; ++i) {
        u64 r = mul2(k00, v[i]);
        r = fma2(k01, b[i*128 + (tid ^ 32)], r);
        r = fma2(k10, b[i*128 + (tid ^ 64)], r);
        v[i] = fma2(k11, b[i*128 + (tid ^ 96)], r);
    }
}

__device__ __forceinline__ void crx_warp_tgt(u64* v, Xch& X, int twb, bool act, float cc, float ss)
{
    u64* b = X.next();
    int tid = X.tid, xv = 32 << twb;
    #pragma unroll
    for (int i = 0; i < 8; ++i) b[i*128 + tid] = v[i];
    __syncthreads();
    float ccl = act ? cc : 1.f, ssl = act ? ss : 0.f;
    u64 cc2 = pk2(ccl, ccl), ssv2 = pk2(ssl, -ssl);
    #pragma unroll
    for (int i = 0; i < 8; ++i)
        v[i] = fma2(cc2, v[i], mul2(ssv2, swap2(b[i*128 + (tid ^ xv)])));
}

__device__ __forceinline__ void crx_rw(u64* v, Xch& X, int twb, float cc, float ss)
{
    u64* b = X.next();
    int tid = X.tid, xv = 32 << twb;
    #pragma unroll
    for (int i = 0; i < 4; ++i) b[i*128 + tid] = v[4 + i];
    __syncthreads();
    u64 cc2 = pk2(cc, cc), ssv2 = pk2(ss, -ss);
    #pragma unroll
    for (int i = 0; i < 4; ++i)
        v[4 + i] = fma2(cc2, v[4 + i], mul2(ssv2, swap2(b[i*128 + (tid ^ xv)])));
}

// -------------------------------------------------------- layer pieces ------
#define SS(A) (sgn*(A).y)

__device__ __forceinline__ void ry_all(u64* v, Xch& X, const float2* __restrict__ ang,
                                       float sgn, int lane)
{
    ry2_warp(v, X, ang[0].x, SS(ang[0]), ang[1].x, SS(ang[1]));  // q0 (bit9) + q1 (bit8)
    ry_reg<2>(v, ang[2].x, SS(ang[2]));
    ry_reg<1>(v, ang[3].x, SS(ang[3]));
    ry_reg<0>(v, ang[4].x, SS(ang[4]));
    #pragma unroll 1
    for (int pl = 4; pl >= 0; --pl) {
        float2 cs = ang[9 - pl];
        ry_lane(v, pl, cs.x, sgn*cs.y, lane);
    }
}

__device__ __forceinline__ void ring_a(u64* v, Xch& X, const float2* __restrict__ ang,
                                       float sgn, int lane, int tid, bool rev)
{
    if (!rev) {
        crx_warp_tgt(v, X, 1, lane & 1, ang[0].x, SS(ang[0]));
        crx_shfl(v, 0, (lane >> 1) & 1, ang[1].x, SS(ang[1]));
        crx_shfl(v, 1, (lane >> 2) & 1, ang[2].x, SS(ang[2]));
        crx_shfl(v, 2, (lane >> 3) & 1, ang[3].x, SS(ang[3]));
        crx_shfl(v, 3, (lane >> 4) & 1, ang[4].x, SS(ang[4]));
        crx_rl<0>(v, 4, ang[5].x, SS(ang[5]));
        crx_rr<1,0>(v, ang[6].x, SS(ang[6]));
        crx_rr<2,1>(v, ang[7].x, SS(ang[7]));
        crx_reg_tgt<2>(v, (tid >> 5) & 1, ang[8].x, SS(ang[8]));
        crx_warp_tgt(v, X, 0, (tid >> 6) & 1, ang[9].x, SS(ang[9]));
    } else {
        crx_warp_tgt(v, X, 0, (tid >> 6) & 1, ang[9].x, SS(ang[9]));
        crx_reg_tgt<2>(v, (tid >> 5) & 1, ang[8].x, SS(ang[8]));
        crx_rr<2,1>(v, ang[7].x, SS(ang[7]));
        crx_rr<1,0>(v, ang[6].x, SS(ang[6]));
        crx_rl<0>(v, 4, ang[5].x, SS(ang[5]));
        crx_shfl(v, 3, (lane >> 4) & 1, ang[4].x, SS(ang[4]));
        crx_shfl(v, 2, (lane >> 3) & 1, ang[3].x, SS(ang[3]));
        crx_shfl(v, 1, (lane >> 2) & 1, ang[2].x, SS(ang[2]));
        crx_shfl(v, 0, (lane >> 1) & 1, ang[1].x, SS(ang[1]));
        crx_warp_tgt(v, X, 1, lane & 1, ang[0].x, SS(ang[0]));
    }
}

__device__ __forceinline__ void ring_b(u64* v, Xch& X, const float2* __restrict__ ang,
                                       float sgn, int lane, int tid, bool rev)
{
    if (!rev) {
        crx_shfl(v, 1, lane & 1, ang[0].x, SS(ang[0]));
        crx_shfl(v, 0, (tid >> 6) & 1, ang[1].x, SS(ang[1]));
        crx_warp_tgt(v, X, 1, (tid >> 5) & 1, ang[2].x, SS(ang[2]));
        crx_rw(v, X, 0, ang[3].x, SS(ang[3]));
        crx_rr<1,2>(v, ang[4].x, SS(ang[4]));
        crx_rr<0,1>(v, ang[5].x, SS(ang[5]));
        crx_reg_tgt<0>(v, (lane >> 4) & 1, ang[6].x, SS(ang[6]));
        crx_shfl(v, 4, (lane >> 3) & 1, ang[7].x, SS(ang[7]));
        crx_shfl(v, 3, (lane >> 2) & 1, ang[8].x, SS(ang[8]));
        crx_shfl(v, 2, (lane >> 1) & 1, ang[9].x, SS(ang[9]));
    } else {
        crx_shfl(v, 2, (lane >> 1) & 1, ang[9].x, SS(ang[9]));
        crx_shfl(v, 3, (lane >> 2) & 1, ang[8].x, SS(ang[8]));
        crx_shfl(v, 4, (lane >> 3) & 1, ang[7].x, SS(ang[7]));
        crx_reg_tgt<0>(v, (lane >> 4) & 1, ang[6].x, SS(ang[6]));
        crx_rr<0,1>(v, ang[5].x, SS(ang[5]));
        crx_rr<1,2>(v, ang[4].x, SS(ang[4]));
        crx_rw(v, X, 0, ang[3].x, SS(ang[3]));
        crx_warp_tgt(v, X, 1, (tid >> 5) & 1, ang[2].x, SS(ang[2]));
        crx_shfl(v, 0, (tid >> 6) & 1, ang[1].x, SS(ang[1]));
        crx_shfl(v, 1, lane & 1, ang[0].x, SS(ang[0]));
    }
}

// --------------------------------------------------- in-register expvals ----
__device__ void exp_partial(int c, int tid, int lane, u64* v, u64* xbuf)
{
    __syncthreads();
    float X[10], Y[10], Z[10];
    #pragma unroll
    for (int i = 0; i < 10; ++i) { X[i] = 0.f; Y[i] = 0.f; Z[i] = 0.f; }

    #pragma unroll
    for (int p = 0; p < 5; ++p) {
        int i = 9 - p;
        int mk = 1 << p;
        float sg = ((lane >> p) & 1) ? -1.f : 1.f;
        #pragma unroll
        for (int q = 0; q < 8; ++q) {
            float2 f = upk(v[q]);
            float px = __shfl_xor_sync(0xffffffffu, f.x, mk);
            float py = __shfl_xor_sync(0xffffffffu, f.y, mk);
            X[i] += f.x*px + f.y*py;
            Y[i] += sg*(f.x*py - f.y*px);
            Z[i] += sg*(f.x*f.x + f.y*f.y);
        }
    }
    #pragma unroll
    for (int pb = 0; pb < 3; ++pb) {
        int i = 4 - pb;
        #pragma unroll
        for (int m = 0; m < 4; ++m) {
            int i0 = ((m >> pb) << (pb+1)) | (m & ((1 << pb) - 1));
            int i1 = i0 | (1 << pb);
            float2 a = upk(v[i0]), cc = upk(v[i1]);
            X[i] += 2.f*(a.x*cc.x + a.y*cc.y);
            Y[i] += 2.f*(a.x*cc.y - a.y*cc.x);
            Z[i] += (a.x*a.x + a.y*a.y) - (cc.x*cc.x + cc.y*cc.y);
        }
    }
    #pragma unroll
    for (int q = 0; q < 8; ++q) xbuf[q*128 + tid] = v[q];
    __syncthreads();
    #pragma unroll
    for (int wb = 0; wb < 2; ++wb) {
        int i = 1 - wb;
        int pr = tid ^ (32 << wb);
        float sg = ((tid >> (5 + wb)) & 1) ? -1.f : 1.f;
        #pragma unroll
        for (int q = 0; q < 8; ++q) {
            float2 g = upk(xbuf[q*128 + pr]);
            float2 f = upk(v[q]);
            X[i] += f.x*g.x + f.y*g.y;
            Y[i] += sg*(f.x*g.y - f.y*g.x);
            Z[i] += sg*(f.x*f.x + f.y*f.y);
        }
    }
    __syncthreads();
    #pragma unroll
    for (int i = 0; i < 10; ++i) {
        #pragma unroll
        for (int off = 16; off; off >>= 1) {
            X[i] += __shfl_down_sync(0xffffffffu, X[i], off);
            Y[i] += __shfl_down_sync(0xffffffffu, Y[i], off);
            Z[i] += __shfl_down_sync(0xffffffffu, Z[i], off);
        }
    }
    float* red = (float*)xbuf;
    int w = tid >> 5;
    if (lane == 0) {
        #pragma unroll
        for (int i = 0; i < 10; ++i) {
            red[w*30 + i]      = X[i];
            red[w*30 + 10 + i] = Y[i];
            red[w*30 + 20 + i] = Z[i];
        }
    }
    __syncthreads();
    if (tid < 30)
        g_expart[c*30 + tid] = red[tid] + red[30 + tid] + red[60 + tid] + red[90 + tid];
}

// ---------------------------------------------------------- select phase ----
__device__ void sel_phase(int c, int tid, int lane, u64* xbuf,
                          const float2* __restrict__ sang, const float2* sv0,
                          int adjoint, int init)
{
    Xch X{xbuf, 0, tid};
    u64 v[8];
    u64* gb = G_STATEU + ((size_t)c << 10);
    int base = (tid >> 5) * 256 + lane;
    if (init) {
        #pragma unroll
        for (int q = 0; q < 8; ++q) v[q] = 0ull;
        if (tid == 0) { float2 f = sv0[c & 15]; v[0] = pk2(f.x, f.y); }
    } else {
        #pragma unroll
        for (int q = 0; q < 8; ++q) v[q] = gb[base + q*32];
    }

    if (!adjoint) {
        const float sgn = 1.f;
        #pragma unroll 1
        for (int l = 0; l < 2; ++l) {
            const float2* a = sang + 40*l;
            ry_all(v, X, a, sgn, lane);
            ring_a(v, X, a + 10, sgn, lane, tid, false);
            ry_all(v, X, a + 20, sgn, lane);
            ring_b(v, X, a + 30, sgn, lane, tid, false);
        }
    } else {
        const float sgn = -1.f;
        #pragma unroll 1
        for (int l = 1; l >= 0; --l) {
            const float2* a = sang + 40*l;
            ring_b(v, X, a + 30, sgn, lane, tid, true);
            ry_all(v, X, a + 20, sgn, lane);
            ring_a(v, X, a + 10, sgn, lane, tid, true);
            ry_all(v, X, a, sgn, lane);
        }
    }

    #pragma unroll
    for (int q = 0; q < 8; ++q) gb[base + q*32] = v[q];
}

// ----- tail: select fwd (2 layers) + qff layer + expvals, register-resident --
__device__ void sel_tail(int c, int tid, int lane, u64* xbuf,
                         const float2* __restrict__ sang,
                         const float2* __restrict__ sqff)
{
    Xch X{xbuf, 0, tid};
    u64 v[8];
    u64* gb = G_STATEU + ((size_t)c << 10);
    int base = (tid >> 5) * 256 + lane;
    #pragma unroll
    for (int q = 0; q < 8; ++q) v[q] = gb[base + q*32];

    const float sgn = 1.f;
    #pragma unroll 1
    for (int l = 0; l < 2; ++l) {
        const float2* a = sang + 40*l;
        ry_all(v, X, a, sgn, lane);
        ring_a(v, X, a + 10, sgn, lane, tid, false);
        ry_all(v, X, a + 20, sgn, lane);
        ring_b(v, X, a + 30, sgn, lane, tid, false);
    }
    // qff layer (F = D3*U^H dropped: ancilla-unitary, commutes w/ qff & obs)
    ry_all(v, X, sqff, sgn, lane);
    ring_a(v, X, sqff + 10, sgn, lane, tid, false);
    ry_all(v, X, sqff + 20, sgn, lane);
    ring_b(v, X, sqff + 30, sgn, lane, tid, false);

    exp_partial(c, tid, lane, v, xbuf);
}

// ------------------------------------------------------------- anc phase ----
__device__ void anc_phase(int c, int tid, int mi, u64* pool)
{
    u64* tile = pool;
    u64* sM   = pool + 1024;
    int b = c >> 4, sc = c & 15;
    sM[tid]       = ((const u64*)g_M[mi])[tid];
    sM[128 + tid] = ((const u64*)g_M[mi])[128 + tid];
    size_t sb = ((size_t)b << 14) + ((size_t)sc << 6);
    #pragma unroll
    for (int i = 0; i < 8; ++i) {
        int idx = i*128 + tid;
        int a = idx >> 6, sj = idx & 63;
        tile[idx] = G_STATEU[sb + ((size_t)a << 10) + sj];
    }
    __syncthreads();
    #pragma unroll
    for (int i = 0; i < 8; ++i) {
        int idx = i*128 + tid;
        int a = idx >> 6, sj = idx & 63;
        u64 acc = 0ull;
        #pragma unroll
        for (int k = 0; k < 16; ++k) {
            float2 m = upk(sM[a*16 + k]);
            u64 xv = tile[k*64 + sj];
            acc = fma2(pk2(m.x, m.x), xv, acc);
            acc = fma2(pk2(-m.y, m.y), swap2(xv), acc);
        }
        G_STATEU[sb + ((size_t)a << 10) + sj] = acc;
    }
}

// -------------------------------------------------------------- mega --------
__global__ void __launch_bounds__(128, 2) mega(
    const float* __restrict__ x,
    const float* __restrict__ Wfp,
    const float* __restrict__ bfp,
    const float* __restrict__ prep_p,
    const float* __restrict__ sig_ang,
    const float* __restrict__ qff_p,
    const float* __restrict__ W_out,
    const float* __restrict__ b_out,
    float* __restrict__ out)
{
    int c = blockIdx.x;
    int bb = c >> 4;
    int cb = c & 15;
    int tid = threadIdx.x;
    int lane = tid & 31;
    __shared__ u64 xbuf[2048];
    __shared__ float2 sang[80];
    __shared__ float2 sqff[40];
    __shared__ float2 sv0[16];
    __shared__ unsigned s_base;
    if (tid == 0) s_base = *(volatile unsigned*)&g_bsns[bb];
    __syncthreads();
    unsigned gen = s_base;

    // ----- P0: local angles, local v0, leader publishes g_M. No batch bar. --
    {
        float* h = (float*)xbuf;
        if (tid < 64) {
            int f = tid;
            int k = f >> 1;
            float div = expf((float)(2*k) * (-logf(10000.0f) / 64.0f));
            float arg = (float)cb * div;
            float pe = (f & 1) ? cosf(arg) : sinf(arg);
            h[f] = x[(bb*64 + f)*16 + cb] + pe;
        }
        __syncthreads();
        if (tid < NROTS) {
            float acc = bfp[tid];
            const float* w = Wfp + tid*64;
            #pragma unroll
            for (int f = 0; f < 64; ++f) acc += h[f]*w[f];
            float sg = 1.0f / (1.0f + expf(-acc));
            float sn, cs;
            sincosf(3.14159265358979323846f * sg, &sn, &cs);
            sang[tid] = make_float2(cs, sn);
        }
        if (tid >= 88 && tid < 88 + QROTS) {
            float cq, sq;
            sincosf(0.5f * qff_p[tid - 88], &sq, &cq);
            sqff[tid - 88] = make_float2(cq, sq);
        }
        __syncthreads();
        float2 (*sU)[16] = (float2(*)[16])(xbuf + 64);
        if (tid < 16) {
            float2 v[16];
            #pragma unroll
            for (int i = 0; i < 16; ++i) v[i] = make_float2(0.f, 0.f);
            v[tid] = make_float2(1.f, 0.f);
            for (int ly = 0; ly < 4; ++ly) {
                for (int qi = 0; qi < 4; ++qi) {
                    int p = 3 - qi;
                    float thy = prep_p[(ly*4 + qi)*2 + 0];
                    float thz = prep_p[(ly*4 + qi)*2 + 1];
                    float cth, sth;
                    sincosf(0.5f*thy, &sth, &cth);
                    for (int m = 0; m < 8; ++m) {
                        int i0 = ((m >> p) << (p+1)) | (m & ((1 << p) - 1));
                        int i1 = i0 | (1 << p);
                        float2 a0 = v[i0], a1 = v[i1];
                        v[i0] = make_float2(cth*a0.x - sth*a1.x, cth*a0.y - sth*a1.y);
                        v[i1] = make_float2(sth*a0.x + cth*a1.x, sth*a0.y + cth*a1.y);
                    }
                    float cz, sz;
                    sincosf(0.5f*thz, &sz, &cz);
                    for (int i = 0; i < 16; ++i) {
                        float im = ((i >> p) & 1) ? sz : -sz;
                        float2 a = v[i];
                        v[i] = make_float2(cz*a.x - im*a.y, cz*a.y + im*a.x);
                    }
                }
                for (int i = 0; i < 3; ++i) {
                    int pc = 3 - i, pt = 2 - i;
                    for (int idx = 0; idx < 16; ++idx) {
                        if (((idx >> pc) & 1) == 1 && ((idx >> pt) & 1) == 0) {
                            int j = idx | (1 << pt);
                            float2 tmp = v[idx]; v[idx] = v[j]; v[j] = tmp;
                        }
                    }
                }
            }
            #pragma unroll
            for (int r = 0; r < 16; ++r) sU[r][tid] = v[r];
        }
        __syncthreads();
        if (tid < 16) {
            float c0, s0;
            sincosf(sig_ang[0], &s0, &c0);
            float2 u = sU[tid][0];
            sv0[tid] = make_float2(c0*u.x - s0*u.y, c0*u.y + s0*u.x);
        }
        if (cb == 0) {
            #pragma unroll 1
            for (int half = 0; half < 2; ++half) {
                int idx = half*128 + tid;
                int j = idx >> 4, k = idx & 15;
                for (int m = 0; m < 2; ++m) {
                    float cp, sp;
                    sincosf(sig_ang[m+1], &sp, &cp);
                    float2 acc = make_float2(0.f, 0.f);
                    #pragma unroll
                    for (int a = 0; a < 16; ++a) {
                        float2 uja = sU[j][a];
                        float2 uka = sU[k][a];
                        float dr = cp, di = (a == 0) ? sp : -sp;
                        float2 dc = make_float2(dr*uka.x + di*uka.y, di*uka.x - dr*uka.y);
                        acc.x += uja.x*dc.x - uja.y*dc.y;
                        acc.y += uja.x*dc.y + uja.y*dc.x;
                    }
                    g_M[m][j*16 + k] = acc;
                }
            }
        }
        __syncthreads();
    }

    sel_phase(c, tid, lane, xbuf, sang, sv0, 0, 1);   // k=0 fwd (init), store
    bbar(bb, gen + 1);
    anc_phase(c, tid, 0, xbuf);
    bbar(bb, gen + 2);
    sel_phase(c, tid, lane, xbuf, sang, sv0, 1, 0);   // k=1 adjoint, store
    bbar(bb, gen + 3);
    anc_phase(c, tid, 1, xbuf);
    bbar(bb, gen + 4);
    sel_tail(c, tid, lane, xbuf, sang, sqff);          // k=2 fwd + qff + exp
    bbar(bb, gen + 5);

    if (cb == 0) {
        float* exf = (float*)sang;
        if (tid < 30) {
            float s = 0.f;
            #pragma unroll
            for (int j = 0; j < 16; ++j) s += g_expart[(bb*16 + j)*30 + tid];
            exf[tid] = s;
        }
        __syncthreads();
        if (tid < ODIM) {
            float acc = b_out[tid];
            #pragma unroll
            for (int j = 0; j < 30; ++j) acc += W_out[tid*30 + j] * exf[j];
            out[bb*ODIM + tid] = acc;
        }
    }
}

// ------------------------------------------------------------ launch --------
extern "C" void kernel_launch(void* const* d_in, const int* in_sizes, int n_in,
                              void* d_out, int out_size)
{
    const float* x       = (const float*)d_in[0];
    const float* W_fp    = (const float*)d_in[1];
    const float* b_fp    = (const float*)d_in[2];
    const float* prep_p  = (const float*)d_in[3];
    const float* sig_ang = (const float*)d_in[4];
    const float* qff_p   = (const float*)d_in[5];
    const float* W_out   = (const float*)d_in[6];
    const float* b_out   = (const float*)d_in[7];
    float* out = (float*)d_out;

    mega<<<NCTA, 128>>>(x, W_fp, b_fp, prep_p, sig_ang, qff_p, W_out, b_out, out);
}